// round 8
// baseline (speedup 1.0000x reference)
#include <cuda_runtime.h>
#include <cuda_fp16.h>
#include <stdint.h>

#define N_NODES 50000
#define N_EDGES 1000000
#define F_IN  64
#define F_HID 64
#define F_OUT 32

#define SCAN_B 256
#define SCAN_NBLK ((N_NODES + SCAN_B - 1) / SCAN_B)   // 196

// ---------------- scratch (device globals: allocation-free rule) ----------------
__device__ __align__(16) __half g_hs1h[N_NODES * F_HID];  // fp16 X@W1 (unscaled)
__device__ __align__(16) float  g_x2  [N_NODES * F_HID];  // relu(agg1 + b1), fp32
__device__ __align__(16) __half g_hs2h[N_NODES * F_OUT];  // fp16 x2@W2 (unscaled)
__device__ float g_dinv[N_NODES];       // rsqrt(deg), deg = cnt+1
__device__ int g_cnt   [N_NODES];
__device__ int g_rowptr[N_NODES + 1];
__device__ int g_cursor[N_NODES];
__device__ int g_csrsrc[N_EDGES];
__device__ int g_bsum  [SCAN_NBLK];
__device__ int g_idx64;                 // 1 if edge_index is int64, 0 if int32

// ---------------- dtype detect + cnt zero (fused) ----------------
__global__ void k_detect_zero(const int* __restrict__ ei32) {
    int i = blockIdx.x * blockDim.x + threadIdx.x;
    if (i < N_NODES) g_cnt[i] = 0;
    if (blockIdx.x == 0) {
        __shared__ int any_nonzero;
        if (threadIdx.x == 0) any_nonzero = 0;
        __syncthreads();
        for (int j = threadIdx.x; j < 2048; j += blockDim.x)
            if (ei32[2 * j + 1] != 0) any_nonzero = 1;
        __syncthreads();
        if (threadIdx.x == 0) g_idx64 = any_nonzero ? 0 : 1;
    }
}

// ---------------- hist: 2 edges per thread, vector index loads ----------------
__global__ void k_hist(const void* __restrict__ ei) {
    int i = blockIdx.x * blockDim.x + threadIdx.x;   // pair index
    if (2 * i >= N_EDGES) return;
    if (g_idx64) {
        longlong2 v = ((const longlong2*)((const long long*)ei + N_EDGES))[i];
        atomicAdd(&g_cnt[(int)v.x], 1);
        atomicAdd(&g_cnt[(int)v.y], 1);
    } else {
        int2 v = ((const int2*)((const int*)ei + N_EDGES))[i];
        atomicAdd(&g_cnt[v.x], 1);
        atomicAdd(&g_cnt[v.y], 1);
    }
}

// ---------------- scan phase 1: per-block sums of g_cnt ----------------
__global__ void __launch_bounds__(SCAN_B) k_blocksums() {
    __shared__ int s[SCAN_B];
    int i = blockIdx.x * SCAN_B + threadIdx.x;
    s[threadIdx.x] = (i < N_NODES) ? g_cnt[i] : 0;
    __syncthreads();
    #pragma unroll
    for (int off = SCAN_B / 2; off > 0; off >>= 1) {
        if (threadIdx.x < off) s[threadIdx.x] += s[threadIdx.x + off];
        __syncthreads();
    }
    if (threadIdx.x == 0) g_bsum[blockIdx.x] = s[0];
}

// ---------------- scan phase 2 (fused): block offset recompute + local scan ----------------
__global__ void __launch_bounds__(SCAN_B) k_rowptr() {
    __shared__ int s[SCAN_B];
    int t = threadIdx.x;
    int i = blockIdx.x * SCAN_B + t;

    // block offset = sum of bsum[j] for j < blockIdx.x  (SCAN_NBLK <= 256)
    s[t] = (t < (int)blockIdx.x && t < SCAN_NBLK) ? g_bsum[t] : 0;
    __syncthreads();
    #pragma unroll
    for (int off = SCAN_B / 2; off > 0; off >>= 1) {
        if (t < off) s[t] += s[t + off];
        __syncthreads();
    }
    int boff = s[0];
    __syncthreads();

    int c = (i < N_NODES) ? g_cnt[i] : 0;
    s[t] = c;
    __syncthreads();
    #pragma unroll
    for (int off = 1; off < SCAN_B; off <<= 1) {
        int v = (t >= off) ? s[t - off] : 0;
        __syncthreads();
        s[t] += v;
        __syncthreads();
    }
    int excl = boff + ((t == 0) ? 0 : s[t - 1]);
    if (i < N_NODES) {
        g_rowptr[i] = excl;
        g_cursor[i] = excl;
        g_dinv[i]   = rsqrtf((float)(c + 1));
    }
    if (i == N_NODES - 1) g_rowptr[N_NODES] = excl + c;
}

// ---------------- permute: 2 edges per thread ----------------
__global__ void k_permute(const void* __restrict__ ei) {
    int i = blockIdx.x * blockDim.x + threadIdx.x;   // pair index
    if (2 * i >= N_EDGES) return;
    int s0, s1, d0, d1;
    if (g_idx64) {
        const long long* p = (const long long*)ei;
        longlong2 sv = ((const longlong2*)p)[i];
        longlong2 dv = ((const longlong2*)(p + N_EDGES))[i];
        s0 = (int)sv.x; s1 = (int)sv.y; d0 = (int)dv.x; d1 = (int)dv.y;
    } else {
        const int* p = (const int*)ei;
        int2 sv = ((const int2*)p)[i];
        int2 dv = ((const int2*)(p + N_EDGES))[i];
        s0 = sv.x; s1 = sv.y; d0 = dv.x; d1 = dv.y;
    }
    g_csrsrc[atomicAdd(&g_cursor[d0], 1)] = s0;
    g_csrsrc[atomicAdd(&g_cursor[d1], 1)] = s1;
}

// ---------------- GEMM1: hs1h = fp16( X @ W1 )  (UNscaled; independent of CSR) ----------------
#define SWZ1(r, k) ((k) ^ ((((r) >> 3) & 3) << 3))
__global__ void __launch_bounds__(128) k_gemm1(const float* __restrict__ x,
                                               const float* __restrict__ W) {
    __shared__ float Xs[128][64];            // 32 KB (swizzled k)
    __shared__ float Ws[64][64];             // 16 KB
    int t = threadIdx.x;
    int row0 = blockIdx.x * 128;

    for (int i = t; i < 64 * 16; i += 128) {
        int k = i >> 4, c = (i & 15) * 4;
        *(float4*)&Ws[k][c] = *(const float4*)(W + k * 64 + c);
    }
    {
        int rl = t >> 4;
        int kg = (t & 15) * 4;
        #pragma unroll
        for (int i = 0; i < 16; i++) {
            int r = rl + i * 8;
            int gr = row0 + r;
            float4 v = make_float4(0.f, 0.f, 0.f, 0.f);
            if (gr < N_NODES) v = *(const float4*)(x + gr * 64 + kg);
            *(float4*)&Xs[r][SWZ1(r, kg)] = v;
        }
    }
    __syncthreads();

    int tx = t & 7, ty = t >> 3;
    int cb = tx * 8, rb = ty * 8;
    float acc[8][8];
    #pragma unroll
    for (int i = 0; i < 8; i++)
        #pragma unroll
        for (int j = 0; j < 8; j++) acc[i][j] = 0.f;

    #pragma unroll
    for (int k = 0; k < 64; k++) {
        float wv[8];
        *(float4*)&wv[0] = *(float4*)&Ws[k][cb];
        *(float4*)&wv[4] = *(float4*)&Ws[k][cb + 4];
        float xv[8];
        #pragma unroll
        for (int i = 0; i < 8; i++) xv[i] = Xs[rb + i][SWZ1(rb + i, k)];
        #pragma unroll
        for (int i = 0; i < 8; i++)
            #pragma unroll
            for (int j = 0; j < 8; j++) acc[i][j] = fmaf(xv[i], wv[j], acc[i][j]);
    }

    #pragma unroll
    for (int i = 0; i < 8; i++) {
        int r = row0 + rb + i;
        if (r < N_NODES) {
            __half2 h[4];
            #pragma unroll
            for (int j = 0; j < 4; j++)
                h[j] = __floats2half2_rn(acc[i][2*j], acc[i][2*j+1]);
            *(uint4*)(g_hs1h + r * 64 + cb) = *(uint4*)h;
        }
    }
}

// ---------------- agg1: x2 = relu( dinv[n]*(dinv[n]*hs[n] + sum dinv[s]*hs[s]) + b1 ) ----------------
// warp per node; lane l owns half2 column l (128B row). Per-edge dinv[src] factor.
__global__ void __launch_bounds__(256) k_agg1(const float* __restrict__ b1) {
    int node = blockIdx.x * 8 + (threadIdx.x >> 5);
    if (node >= N_NODES) return;
    int lane = threadIdx.x & 31;
    const __half2* hs = (const __half2*)g_hs1h;

    int start = g_rowptr[node], end = g_rowptr[node + 1];
    float dn = g_dinv[node];
    float2 f = __half22float2(hs[node * 32 + lane]);        // self-loop
    float2 acc = make_float2(f.x * dn, f.y * dn);

    int e = start;
    for (; e + 4 <= end; e += 4) {
        int s0 = g_csrsrc[e + 0], s1 = g_csrsrc[e + 1];
        int s2 = g_csrsrc[e + 2], s3 = g_csrsrc[e + 3];
        float d0 = g_dinv[s0], d1 = g_dinv[s1], d2 = g_dinv[s2], d3 = g_dinv[s3];
        float2 f0 = __half22float2(hs[s0 * 32 + lane]);
        float2 f1 = __half22float2(hs[s1 * 32 + lane]);
        float2 f2 = __half22float2(hs[s2 * 32 + lane]);
        float2 f3 = __half22float2(hs[s3 * 32 + lane]);
        acc.x += f0.x * d0 + f1.x * d1 + f2.x * d2 + f3.x * d3;
        acc.y += f0.y * d0 + f1.y * d1 + f2.y * d2 + f3.y * d3;
    }
    for (; e < end; e++) {
        int s0 = g_csrsrc[e];
        float d0 = g_dinv[s0];
        float2 v = __half22float2(hs[s0 * 32 + lane]);
        acc.x += v.x * d0; acc.y += v.y * d0;
    }

    float2 bb = *(const float2*)(b1 + 2 * lane);
    float2 o;
    o.x = fmaxf(fmaf(acc.x, dn, bb.x), 0.f);
    o.y = fmaxf(fmaf(acc.y, dn, bb.y), 0.f);
    *(float2*)(g_x2 + node * 64 + 2 * lane) = o;
}

// ---------------- GEMM2: hs2h = fp16( x2 @ W2 )  (UNscaled) ----------------
__global__ void __launch_bounds__(128) k_gemm2(const float* __restrict__ W) {
    __shared__ float Xs[128][65];
    __shared__ float Ws[64][32];
    int t = threadIdx.x;
    int row0 = blockIdx.x * 128;

    for (int i = t; i < 64 * 8; i += 128) {
        int k = i >> 3, c = (i & 7) * 4;
        *(float4*)&Ws[k][c] = *(const float4*)(W + k * 32 + c);
    }
    {
        int rl = t >> 4;
        int kg = (t & 15) * 4;
        #pragma unroll
        for (int i = 0; i < 16; i++) {
            int r = rl + i * 8;
            int gr = row0 + r;
            float4 v = make_float4(0.f, 0.f, 0.f, 0.f);
            if (gr < N_NODES) v = *(const float4*)(g_x2 + gr * 64 + kg);
            Xs[r][kg] = v.x; Xs[r][kg + 1] = v.y; Xs[r][kg + 2] = v.z; Xs[r][kg + 3] = v.w;
        }
    }
    __syncthreads();

    int tx = t & 7, ty = t >> 3;
    int cb = tx * 4, rb = ty * 8;
    float acc[8][4];
    #pragma unroll
    for (int i = 0; i < 8; i++)
        #pragma unroll
        for (int j = 0; j < 4; j++) acc[i][j] = 0.f;

    #pragma unroll
    for (int k = 0; k < 64; k++) {
        float wv[4];
        *(float4*)&wv[0] = *(float4*)&Ws[k][cb];
        float xv[8];
        #pragma unroll
        for (int i = 0; i < 8; i++) xv[i] = Xs[rb + i][k];
        #pragma unroll
        for (int i = 0; i < 8; i++)
            #pragma unroll
            for (int j = 0; j < 4; j++) acc[i][j] = fmaf(xv[i], wv[j], acc[i][j]);
    }

    #pragma unroll
    for (int i = 0; i < 8; i++) {
        int r = row0 + rb + i;
        if (r < N_NODES) {
            __half2 h[2];
            h[0] = __floats2half2_rn(acc[i][0], acc[i][1]);
            h[1] = __floats2half2_rn(acc[i][2], acc[i][3]);
            *(uint2*)(g_hs2h + r * 32 + cb) = *(uint2*)h;
        }
    }
}

// ---------------- agg2: out = dinv[n]*(dinv[n]*hs2[n] + sum dinv[s]*hs2[s]) + b2 ----------------
// warp per node; 2 sub-warps of 16 lanes alternate edges; lane owns half2 col.
__global__ void __launch_bounds__(256) k_agg2(float* __restrict__ out,
                                              const float* __restrict__ b2) {
    int node = blockIdx.x * 8 + (threadIdx.x >> 5);
    if (node >= N_NODES) return;
    int lane = threadIdx.x & 31;
    int sub = lane >> 4;
    int c = lane & 15;
    const __half2* hs = (const __half2*)g_hs2h;

    int start = g_rowptr[node], end = g_rowptr[node + 1];
    float dn = g_dinv[node];
    float2 acc = make_float2(0.f, 0.f);
    if (sub == 0) {
        float2 f = __half22float2(hs[node * 16 + c]);       // self-loop
        acc.x = f.x * dn; acc.y = f.y * dn;
    }
    int e = start + sub;
    for (; e + 2 < end; e += 4) {            // reads e and e+2: need e+2 <= end-1
        int s0 = g_csrsrc[e], s1 = g_csrsrc[e + 2];
        float d0 = g_dinv[s0], d1 = g_dinv[s1];
        float2 f0 = __half22float2(hs[s0 * 16 + c]);
        float2 f1 = __half22float2(hs[s1 * 16 + c]);
        acc.x += f0.x * d0 + f1.x * d1;
        acc.y += f0.y * d0 + f1.y * d1;
    }
    if (e < end) {
        int s0 = g_csrsrc[e];
        float d0 = g_dinv[s0];
        float2 f = __half22float2(hs[s0 * 16 + c]);
        acc.x += f.x * d0; acc.y += f.y * d0;
    }
    acc.x += __shfl_xor_sync(0xffffffffu, acc.x, 16);
    acc.y += __shfl_xor_sync(0xffffffffu, acc.y, 16);
    if (sub == 0) {
        float2 bb = *(const float2*)(b2 + 2 * c);
        float2 o = make_float2(fmaf(acc.x, dn, bb.x), fmaf(acc.y, dn, bb.y));
        *(float2*)(out + node * 32 + 2 * c) = o;
    }
}

// ---------------- side-stream resources (CPU objects, created once) ----------------
struct SideRes {
    cudaStream_t s;
    cudaEvent_t fork, join;
    SideRes() {
        cudaStreamCreateWithFlags(&s, cudaStreamNonBlocking);
        cudaEventCreateWithFlags(&fork, cudaEventDisableTiming);
        cudaEventCreateWithFlags(&join, cudaEventDisableTiming);
    }
};
static SideRes& side() { static SideRes r; return r; }

// ----------------------------------------------------------------
extern "C" void kernel_launch(void* const* d_in, const int* in_sizes, int n_in,
                              void* d_out, int out_size) {
    const float* x  = (const float*)d_in[0];
    const void*  ei = d_in[1];
    const float* W1 = (const float*)d_in[2];
    const float* b1 = (const float*)d_in[3];
    const float* W2 = (const float*)d_in[4];
    const float* b2 = (const float*)d_in[5];

    SideRes& r = side();

    // fork: gemm1 (independent of edges) runs concurrently with CSR build
    cudaEventRecord(r.fork, (cudaStream_t)0);
    cudaStreamWaitEvent(r.s, r.fork, 0);
    k_gemm1<<<(N_NODES + 127) / 128, 128, 0, r.s>>>(x, W1);
    cudaEventRecord(r.join, r.s);

    // main stream: CSR build
    k_detect_zero<<<SCAN_NBLK, 256>>>((const int*)ei);
    k_hist      <<<(N_EDGES / 2 + 255) / 256, 256>>>(ei);
    k_blocksums <<<SCAN_NBLK, SCAN_B>>>();
    k_rowptr    <<<SCAN_NBLK, SCAN_B>>>();
    k_permute   <<<(N_EDGES / 2 + 255) / 256, 256>>>(ei);

    // join, then the dependent chain
    cudaStreamWaitEvent((cudaStream_t)0, r.join, 0);
    k_agg1 <<<(N_NODES + 7) / 8, 256>>>(b1);
    k_gemm2<<<(N_NODES + 127) / 128, 128>>>(W2);
    k_agg2 <<<(N_NODES + 7) / 8, 256>>>((float*)d_out, b2);
}